// round 8
// baseline (speedup 1.0000x reference)
#include <cuda_runtime.h>
#include <cuda_bf16.h>
#include <cstdint>

#define VOCAB  32000
#define HIDDEN 4096
#define NTOK   4096      // 8*512 tokens
#define SEQ    512
#define NP     250       // VOCAB / 128 partial tiles per row
#define IGNORE_INDEX (-100)

#define BK     32                // bf16 per K block
#define NKB    (HIDDEN / BK)     // 128
#define NSTAGE 5
#define ROWB   80                // padded row stride in bytes (40 bf16)
#define ABYTES (128 * ROWB)      // 10240 per operand per stage
#define STAGEB (2 * ABYTES)      // 20480 (A then B)
#define OFF_RED (NSTAGE * STAGEB)            // 102400
#define SMEM_BYTES (OFF_RED + 128 * 2 * 8)   // + red[128][2] float2 = 104448

// ---------------- scratch (device globals; no allocation allowed) ----------
__device__ __align__(128) __nv_bfloat16 g_W[(size_t)VOCAB * HIDDEN];  // 262 MB
__device__ __align__(128) __nv_bfloat16 g_X[(size_t)NTOK * HIDDEN];   // 33 MB
__device__ float g_pmax[(size_t)NTOK * NP];
__device__ float g_psum[(size_t)NTOK * NP];
__device__ float g_tgt[NTOK];
__device__ float g_ptok[NTOK];

// ---------------- small asm helpers ----------------------------------------
__device__ __forceinline__ uint32_t smem_u32(const void* p) {
    uint32_t a;
    asm("{ .reg .u64 t; cvta.to.shared.u64 t, %1; cvt.u32.u64 %0, t; }"
        : "=r"(a) : "l"(p));
    return a;
}
#define CP_ASYNC16(dst, src) \
    asm volatile("cp.async.cg.shared.global [%0], [%1], 16;" :: "r"(dst), "l"(src))
#define CP_COMMIT() asm volatile("cp.async.commit_group;" ::: "memory")
#define CP_WAIT(n)  asm volatile("cp.async.wait_group %0;" :: "n"(n) : "memory")

#define LDMATRIX_X4(r0, r1, r2, r3, addr) \
    asm volatile("ldmatrix.sync.aligned.m8n8.x4.shared.b16 {%0,%1,%2,%3}, [%4];" \
                 : "=r"(r0), "=r"(r1), "=r"(r2), "=r"(r3) : "r"(addr))

__device__ __forceinline__ void mma16816(float c[4],
                                         uint32_t a0, uint32_t a1, uint32_t a2, uint32_t a3,
                                         uint32_t b0, uint32_t b1) {
    asm volatile(
        "mma.sync.aligned.m16n8k16.row.col.f32.bf16.bf16.f32 "
        "{%0,%1,%2,%3}, {%4,%5,%6,%7}, {%8,%9}, {%0,%1,%2,%3};\n"
        : "+f"(c[0]), "+f"(c[1]), "+f"(c[2]), "+f"(c[3])
        : "r"(a0), "r"(a1), "r"(a2), "r"(a3), "r"(b0), "r"(b1));
}

// ---------------- fp32 -> bf16 conversion ----------------------------------
__global__ void conv_kernel(const float4* __restrict__ src,
                            __nv_bfloat162* __restrict__ dst, int n4) {
    for (int i = blockIdx.x * blockDim.x + threadIdx.x; i < n4;
         i += gridDim.x * blockDim.x) {
        float4 v = src[i];
        dst[2 * i]     = __floats2bfloat162_rn(v.x, v.y);
        dst[2 * i + 1] = __floats2bfloat162_rn(v.z, v.w);
    }
}

// ---------------- exact fp32 target logits ----------------------------------
__global__ void tgt_kernel(const float* __restrict__ x,
                           const float* __restrict__ w,
                           const float* __restrict__ bias,
                           const int* __restrict__ target) {
    const int row  = blockIdx.x * 8 + (threadIdx.x >> 5);
    const int lane = threadIdx.x & 31;
    const int t = target[row];
    if (t == IGNORE_INDEX) {
        if (lane == 0) g_tgt[row] = 0.f;
        return;
    }
    const float4* xr = reinterpret_cast<const float4*>(x + (size_t)row * HIDDEN);
    const float4* wr = reinterpret_cast<const float4*>(w + (size_t)t * HIDDEN);
    float s = 0.f;
#pragma unroll 4
    for (int j = lane; j < HIDDEN / 4; j += 32) {
        float4 a = xr[j];
        float4 b = wr[j];
        s += a.x * b.x + a.y * b.y + a.z * b.z + a.w * b.w;
    }
#pragma unroll
    for (int off = 16; off; off >>= 1)
        s += __shfl_xor_sync(0xffffffffu, s, off);
    if (lane == 0) g_tgt[row] = s + bias[t];
}

// ---------------- stage loader: cp.async GMEM bf16 -> padded SMEM -----------
// 128 threads: 512 16B chunks per operand per stage -> 4 per thread each.
__device__ __forceinline__ void load_stage(uint32_t sb, int slot, int kb,
                                           int m0, int n0, int tid) {
    const uint32_t base = sb + slot * STAGEB;
#pragma unroll
    for (int h = 0; h < 4; h++) {
        const int c   = tid + h * 128;
        const int row = c >> 2;
        const int seg = c & 3;
        const uint32_t dA = base + row * ROWB + seg * 16;
        const __nv_bfloat16* sA = g_X + (size_t)(m0 + row) * HIDDEN + kb * BK + seg * 8;
        CP_ASYNC16(dA, sA);
        const uint32_t dB = base + ABYTES + row * ROWB + seg * 16;
        const __nv_bfloat16* sB = g_W + (size_t)(n0 + row) * HIDDEN + kb * BK + seg * 8;
        CP_ASYNC16(dB, sB);
    }
}

// ---------------- bf16 GEMM (ldmatrix + mma.16816) + fused LSE --------------
// Grid (32 m-tiles [fast], 250 n-tiles). 128 threads, 4 warps (2x2).
// CTA tile 128x128, warp tile 64x64, BK=32, 5-stage ring, barrier per 2 kb,
// double-buffered fragments (LDSM of half h+1 overlaps MMA of half h).
__global__ __launch_bounds__(128, 2)
void gemm_lse_kernel(const float* __restrict__ bias) {
    extern __shared__ char smem[];
    const uint32_t sb = smem_u32(smem);

    const int tid  = threadIdx.x;
    const int lane = tid & 31;
    const int warp = tid >> 5;
    const int g    = lane >> 2;     // 0..7
    const int tig  = lane & 3;      // 0..3
    const int wm   = warp >> 1;     // 0..1 : rows wm*64..+63
    const int wn   = warp & 1;      // 0..1 : cols wn*64..+63
    const int m0   = blockIdx.x * 128;
    const int n0   = blockIdx.y * 128;

    float acc[4][8][4];
#pragma unroll
    for (int i = 0; i < 4; i++)
#pragma unroll
        for (int j = 0; j < 8; j++)
#pragma unroll
            for (int k = 0; k < 4; k++) acc[i][j][k] = 0.f;

    // prologue: stages 0,1,2 in flight (slots 0,1,2)
    load_stage(sb, 0, 0, m0, n0, tid); CP_COMMIT();
    load_stage(sb, 1, 1, m0, n0, tid); CP_COMMIT();
    load_stage(sb, 2, 2, m0, n0, tid); CP_COMMIT();

    // ldmatrix per-thread byte offsets (constant across stages)
    const int a_row  = lane & 15;
    const int a_col8 = (lane >> 4) & 1;
    const int b_n    = ((lane >> 4) & 1) * 8 + (lane & 7);
    const int b_k8   = (lane >> 3) & 1;
    uint32_t offA[4], offB[4];
#pragma unroll
    for (int mt = 0; mt < 4; mt++)
        offA[mt] = (wm * 64 + mt * 16 + a_row) * ROWB + a_col8 * 16;
#pragma unroll
    for (int np = 0; np < 4; np++)
        offB[np] = ABYTES + (wn * 64 + np * 16 + b_n) * ROWB + b_k8 * 16;

    uint32_t fa[2][4][4], fb[2][8][2];

    // fragment loader for one k16-half at SMEM stage base (+kh*32 bytes)
#define LD_FRAGS(p, base, khoff) do {                                          \
        const uint32_t _b = (base) + (khoff);                                  \
        _Pragma("unroll")                                                      \
        for (int mt = 0; mt < 4; mt++)                                         \
            LDMATRIX_X4(fa[p][mt][0], fa[p][mt][1], fa[p][mt][2], fa[p][mt][3],\
                        _b + offA[mt]);                                        \
        _Pragma("unroll")                                                      \
        for (int np = 0; np < 4; np++) {                                       \
            uint32_t r0, r1, r2, r3;                                           \
            LDMATRIX_X4(r0, r1, r2, r3, _b + offB[np]);                        \
            fb[p][np * 2][0] = r0;     fb[p][np * 2][1] = r1;                  \
            fb[p][np * 2 + 1][0] = r2; fb[p][np * 2 + 1][1] = r3;              \
        }                                                                      \
    } while (0)

#define MMA_HALF(p) do {                                                       \
        _Pragma("unroll")                                                      \
        for (int mt = 0; mt < 4; mt++)                                         \
            _Pragma("unroll")                                                  \
            for (int nt = 0; nt < 8; nt++)                                     \
                mma16816(acc[mt][nt], fa[p][mt][0], fa[p][mt][1],              \
                         fa[p][mt][2], fa[p][mt][3],                           \
                         fb[p][nt][0], fb[p][nt][1]);                          \
    } while (0)

    int slot0 = 0;   // (2j) % 5, maintained incrementally
    for (int j = 0; j < NKB / 2; j++) {
        const int kb2 = 2 * j;
        if (j < NKB / 2 - 1) CP_WAIT(1);
        else                 CP_WAIT(0);
        __syncthreads();

        // issue loads for stages kb2+3, kb2+4 (slots distinct from reads mod 5)
        const int s1 = kb2 + 3, s2 = kb2 + 4;
        int slot1 = slot0 + 3; if (slot1 >= 5) slot1 -= 5;
        int slot2 = slot0 + 4; if (slot2 >= 5) slot2 -= 5;
        if (s1 < NKB) { load_stage(sb, slot1, s1, m0, n0, tid); CP_COMMIT(); }
        if (s2 < NKB) { load_stage(sb, slot2, s2, m0, n0, tid); CP_COMMIT(); }

        const uint32_t base0 = sb + slot0 * STAGEB;
        int slotn = slot0 + 1; if (slotn >= 5) slotn -= 5;
        const uint32_t base1 = sb + slotn * STAGEB;

        // 4 k16-halves: stage base0 (kh 0,1) then base1 (kh 0,1), pipelined
        LD_FRAGS(0, base0, 0);
        LD_FRAGS(1, base0, 32);
        MMA_HALF(0);
        LD_FRAGS(0, base1, 0);
        MMA_HALF(1);
        LD_FRAGS(1, base1, 32);
        MMA_HALF(0);
        MMA_HALF(1);

        slot0 += 2; if (slot0 >= 5) slot0 -= 5;
    }
    __syncthreads();   // SMEM now reusable for reduction

    // --------- fused epilogue: bias + row (max, sumexp) partials ------------
    float2 (*red)[2] = (float2(*)[2])(smem + OFF_RED);
#pragma unroll
    for (int mt = 0; mt < 4; mt++) {
#pragma unroll
        for (int half = 0; half < 2; half++) {
            const int rloc = wm * 64 + mt * 16 + g + half * 8;
            float v[16];
            float vmax = -1e30f;
#pragma unroll
            for (int nt = 0; nt < 8; nt++) {
                const int c0g = n0 + wn * 64 + nt * 8 + tig * 2;
                float v0 = acc[mt][nt][half * 2 + 0] + bias[c0g];
                float v1 = acc[mt][nt][half * 2 + 1] + bias[c0g + 1];
                v[nt * 2]     = v0;
                v[nt * 2 + 1] = v1;
                vmax = fmaxf(vmax, fmaxf(v0, v1));
            }
            float vsum = 0.f;
#pragma unroll
            for (int jj = 0; jj < 16; jj++) vsum += __expf(v[jj] - vmax);
#pragma unroll
            for (int off = 1; off < 4; off <<= 1) {
                float om = __shfl_xor_sync(0xffffffffu, vmax, off);
                float os = __shfl_xor_sync(0xffffffffu, vsum, off);
                float nm = fmaxf(vmax, om);
                vsum = vsum * __expf(vmax - nm) + os * __expf(om - nm);
                vmax = nm;
            }
            if (tig == 0) red[rloc][wn] = make_float2(vmax, vsum);
        }
    }
    __syncthreads();
    if (tid < 128) {
        float m = -1e30f, s = 0.f;
#pragma unroll
        for (int w = 0; w < 2; w++) {
            float2 p = red[tid][w];
            float nm = fmaxf(m, p.x);
            s = s * __expf(m - nm) + p.y * __expf(p.x - nm);
            m = nm;
        }
        const size_t idx = (size_t)(m0 + tid) * NP + blockIdx.y;
        g_pmax[idx] = m;
        g_psum[idx] = s;
    }
}

// ---------------- combine partials -> per-token logp ------------------------
__global__ void lse_kernel(const int* __restrict__ target) {
    const int row  = blockIdx.x * 8 + (threadIdx.x >> 5);
    const int lane = threadIdx.x & 31;
    const float* pm = g_pmax + (size_t)row * NP;
    const float* ps = g_psum + (size_t)row * NP;
    float m = -1e30f, s = 0.f;
    for (int j = lane; j < NP; j += 32) {
        float om = pm[j], os = ps[j];
        float nm = fmaxf(m, om);
        s = s * __expf(m - nm) + os * __expf(om - nm);
        m = nm;
    }
#pragma unroll
    for (int off = 16; off; off >>= 1) {
        float om = __shfl_xor_sync(0xffffffffu, m, off);
        float os = __shfl_xor_sync(0xffffffffu, s, off);
        float nm = fmaxf(m, om);
        s = s * __expf(m - nm) + os * __expf(om - nm);
        m = nm;
    }
    if (lane == 0) {
        const float lse = m + logf(s);
        const int t = target[row];
        g_ptok[row] = (t != IGNORE_INDEX) ? (g_tgt[row] - lse) : 0.f;
    }
}

// ---------------- final scalar loss -----------------------------------------
__global__ void final_kernel(const int* __restrict__ target,
                             const float* __restrict__ ref_c,
                             const float* __restrict__ ref_r,
                             float* __restrict__ out) {
    __shared__ float ssum[8];
    __shared__ float scnt[8];
    const int warp = threadIdx.x >> 5;
    const int lane = threadIdx.x & 31;
    float s = 0.f, c = 0.f;
    for (int t = lane; t < SEQ; t += 32) {
        const int row = warp * SEQ + t;
        if (target[row] != IGNORE_INDEX) {
            s += g_ptok[row];
            c += 1.f;
        }
    }
#pragma unroll
    for (int off = 16; off; off >>= 1) {
        s += __shfl_xor_sync(0xffffffffu, s, off);
        c += __shfl_xor_sync(0xffffffffu, c, off);
    }
    if (lane == 0) { ssum[warp] = s; scnt[warp] = c; }
    __syncthreads();
    if (threadIdx.x == 0) {
        float nll_num = 0.f, nll_den = 0.f;
        for (int b = 0; b < 4; b++) { nll_num += ssum[b]; nll_den += scnt[b]; }
        const float nll = -nll_num / nll_den;
        float pl = 0.f;
        for (int i = 0; i < 4; i++) {
            const float ca = ssum[i] / scnt[i] - ref_c[i];
            const float ra = ssum[4 + i] / scnt[4 + i] - ref_r[i];
            const float x  = 0.1f * (ca - ra);
            const float ls = fminf(x, 0.f) - log1pf(expf(-fabsf(x)));
            pl -= ls;
        }
        pl *= 0.25f;
        out[0] = pl + nll;
    }
}

// ---------------- launcher ---------------------------------------------------
extern "C" void kernel_launch(void* const* d_in, const int* in_sizes, int n_in,
                              void* d_out, int out_size) {
    const float* lin_w = (const float*)d_in[0];
    const float* x     = (const float*)d_in[1];
    const int*   tgt   = (const int*)d_in[2];
    const float* ref_c = (const float*)d_in[3];
    const float* ref_r = (const float*)d_in[4];
    const float* bias  = (const float*)d_in[5];
    float* out = (float*)d_out;

    cudaFuncSetAttribute(gemm_lse_kernel,
                         cudaFuncAttributeMaxDynamicSharedMemorySize, SMEM_BYTES);

    __nv_bfloat162* dW;
    __nv_bfloat162* dX;
    cudaGetSymbolAddress((void**)&dW, g_W);
    cudaGetSymbolAddress((void**)&dX, g_X);

    conv_kernel<<<2048, 256>>>((const float4*)lin_w, dW, VOCAB * HIDDEN / 4);
    conv_kernel<<<512, 256>>>((const float4*)x, dX, NTOK * HIDDEN / 4);

    tgt_kernel<<<NTOK / 8, 256>>>(x, lin_w, bias, tgt);

    dim3 grid(NTOK / 128, NP);   // m fast-varying -> B panel shared in-wave
    gemm_lse_kernel<<<grid, 128, SMEM_BYTES>>>(bias);

    lse_kernel<<<NTOK / 8, 256>>>(tgt);
    final_kernel<<<1, 256>>>(tgt, ref_c, ref_r, out);
}

// round 9
// speedup vs baseline: 1.0591x; 1.0591x over previous
#include <cuda_runtime.h>
#include <cuda_bf16.h>
#include <cstdint>

#define VOCAB  32000
#define HIDDEN 4096
#define NTOK   4096      // 8*512 tokens
#define SEQ    512
#define NP     250       // VOCAB / 128 partial tiles per row
#define IGNORE_INDEX (-100)

#define BK     64                // bf16 per K block (128 bytes)
#define NKB    (HIDDEN / BK)     // 64
#define NSTAGE 3
#define ROWB   144               // 128B row + 16B pad (conflict-free LDSM)
#define ABYTES (128 * ROWB)      // 18432 per operand per stage
#define STAGEB (2 * ABYTES)      // 36864 (A then B)
#define OFF_RED (NSTAGE * STAGEB)            // 110592
#define SMEM_BYTES (OFF_RED + 128 * 2 * 8)   // + red[128][2] float2 = 112640

// ---------------- scratch (device globals; no allocation allowed) ----------
__device__ __align__(128) __nv_bfloat16 g_W[(size_t)VOCAB * HIDDEN];  // 262 MB
__device__ __align__(128) __nv_bfloat16 g_X[(size_t)NTOK * HIDDEN];   // 33 MB
__device__ float g_pmax[(size_t)NTOK * NP];
__device__ float g_psum[(size_t)NTOK * NP];
__device__ float g_tgt[NTOK];
__device__ float g_ptok[NTOK];

// ---------------- small asm helpers ----------------------------------------
__device__ __forceinline__ uint32_t smem_u32(const void* p) {
    uint32_t a;
    asm("{ .reg .u64 t; cvta.to.shared.u64 t, %1; cvt.u32.u64 %0, t; }"
        : "=r"(a) : "l"(p));
    return a;
}
#define CP_ASYNC16(dst, src) \
    asm volatile("cp.async.cg.shared.global [%0], [%1], 16;" :: "r"(dst), "l"(src))
#define CP_COMMIT() asm volatile("cp.async.commit_group;" ::: "memory")
#define CP_WAIT(n)  asm volatile("cp.async.wait_group %0;" :: "n"(n) : "memory")

#define LDMATRIX_X4(r0, r1, r2, r3, addr) \
    asm volatile("ldmatrix.sync.aligned.m8n8.x4.shared.b16 {%0,%1,%2,%3}, [%4];" \
                 : "=r"(r0), "=r"(r1), "=r"(r2), "=r"(r3) : "r"(addr))

__device__ __forceinline__ void mma16816(float c[4],
                                         uint32_t a0, uint32_t a1, uint32_t a2, uint32_t a3,
                                         uint32_t b0, uint32_t b1) {
    asm volatile(
        "mma.sync.aligned.m16n8k16.row.col.f32.bf16.bf16.f32 "
        "{%0,%1,%2,%3}, {%4,%5,%6,%7}, {%8,%9}, {%0,%1,%2,%3};\n"
        : "+f"(c[0]), "+f"(c[1]), "+f"(c[2]), "+f"(c[3])
        : "r"(a0), "r"(a1), "r"(a2), "r"(a3), "r"(b0), "r"(b1));
}

// ---------------- fp32 -> bf16 conversion ----------------------------------
__global__ void conv_kernel(const float4* __restrict__ src,
                            __nv_bfloat162* __restrict__ dst, int n4) {
    for (int i = blockIdx.x * blockDim.x + threadIdx.x; i < n4;
         i += gridDim.x * blockDim.x) {
        float4 v = src[i];
        dst[2 * i]     = __floats2bfloat162_rn(v.x, v.y);
        dst[2 * i + 1] = __floats2bfloat162_rn(v.z, v.w);
    }
}

// ---------------- exact fp32 target logits ----------------------------------
__global__ void tgt_kernel(const float* __restrict__ x,
                           const float* __restrict__ w,
                           const float* __restrict__ bias,
                           const int* __restrict__ target) {
    const int row  = blockIdx.x * 8 + (threadIdx.x >> 5);
    const int lane = threadIdx.x & 31;
    const int t = target[row];
    if (t == IGNORE_INDEX) {
        if (lane == 0) g_tgt[row] = 0.f;
        return;
    }
    const float4* xr = reinterpret_cast<const float4*>(x + (size_t)row * HIDDEN);
    const float4* wr = reinterpret_cast<const float4*>(w + (size_t)t * HIDDEN);
    float s = 0.f;
#pragma unroll 4
    for (int j = lane; j < HIDDEN / 4; j += 32) {
        float4 a = xr[j];
        float4 b = wr[j];
        s += a.x * b.x + a.y * b.y + a.z * b.z + a.w * b.w;
    }
#pragma unroll
    for (int off = 16; off; off >>= 1)
        s += __shfl_xor_sync(0xffffffffu, s, off);
    if (lane == 0) g_tgt[row] = s + bias[t];
}

// ---------------- stage loader: cp.async GMEM bf16 -> padded SMEM -----------
// 128 threads: rows of 128B = 8 chunks; 1024 chunks per operand -> 8/thread.
__device__ __forceinline__ void load_stage(uint32_t sb, int slot, int kb,
                                           int m0, int n0, int tid) {
    const uint32_t base = sb + slot * STAGEB;
#pragma unroll
    for (int h = 0; h < 8; h++) {
        const int c   = tid + h * 128;
        const int row = c >> 3;
        const int seg = c & 7;
        const uint32_t dA = base + row * ROWB + seg * 16;
        const __nv_bfloat16* sA = g_X + (size_t)(m0 + row) * HIDDEN + kb * BK + seg * 8;
        CP_ASYNC16(dA, sA);
        const uint32_t dB = base + ABYTES + row * ROWB + seg * 16;
        const __nv_bfloat16* sB = g_W + (size_t)(n0 + row) * HIDDEN + kb * BK + seg * 8;
        CP_ASYNC16(dB, sB);
    }
}

// ---------------- bf16 GEMM (ldmatrix + mma.16816) + fused LSE --------------
// Grid (32 m-tiles [fast], 250 n-tiles). 128 threads, 4 warps (2x2).
// CTA tile 128x128, warp tile 64x64, BK=64, 3-stage ring (prefetch dist 2),
// fragment double-buffer across the 4 k16-halves within one (visible) stage.
__global__ __launch_bounds__(128, 2)
void gemm_lse_kernel(const float* __restrict__ bias) {
    extern __shared__ char smem[];
    const uint32_t sb = smem_u32(smem);

    const int tid  = threadIdx.x;
    const int lane = tid & 31;
    const int warp = tid >> 5;
    const int g    = lane >> 2;     // 0..7
    const int tig  = lane & 3;      // 0..3
    const int wm   = warp >> 1;     // 0..1 : rows wm*64..+63
    const int wn   = warp & 1;      // 0..1 : cols wn*64..+63
    const int m0   = blockIdx.x * 128;
    const int n0   = blockIdx.y * 128;

    float acc[4][8][4];
#pragma unroll
    for (int i = 0; i < 4; i++)
#pragma unroll
        for (int j = 0; j < 8; j++)
#pragma unroll
            for (int k = 0; k < 4; k++) acc[i][j][k] = 0.f;

    // prologue: stages 0,1 in flight (slots 0,1)
    load_stage(sb, 0, 0, m0, n0, tid); CP_COMMIT();
    load_stage(sb, 1, 1, m0, n0, tid); CP_COMMIT();

    // ldmatrix per-thread byte offsets (constant across stages)
    const int a_row  = lane & 15;
    const int a_col8 = (lane >> 4) & 1;
    const int b_n    = ((lane >> 4) & 1) * 8 + (lane & 7);
    const int b_k8   = (lane >> 3) & 1;
    uint32_t offA[4], offB[4];
#pragma unroll
    for (int mt = 0; mt < 4; mt++)
        offA[mt] = (wm * 64 + mt * 16 + a_row) * ROWB + a_col8 * 16;
#pragma unroll
    for (int np = 0; np < 4; np++)
        offB[np] = ABYTES + (wn * 64 + np * 16 + b_n) * ROWB + b_k8 * 16;

    uint32_t fa[2][4][4], fb[2][8][2];

    // fragment loader for one k16-half (khoff bytes within the 128B row)
#define LD_FRAGS(p, base, khoff) do {                                          \
        const uint32_t _b = (base) + (khoff);                                  \
        _Pragma("unroll")                                                      \
        for (int mt = 0; mt < 4; mt++)                                         \
            LDMATRIX_X4(fa[p][mt][0], fa[p][mt][1], fa[p][mt][2], fa[p][mt][3],\
                        _b + offA[mt]);                                        \
        _Pragma("unroll")                                                      \
        for (int np = 0; np < 4; np++) {                                       \
            uint32_t r0, r1, r2, r3;                                           \
            LDMATRIX_X4(r0, r1, r2, r3, _b + offB[np]);                        \
            fb[p][np * 2][0] = r0;     fb[p][np * 2][1] = r1;                  \
            fb[p][np * 2 + 1][0] = r2; fb[p][np * 2 + 1][1] = r3;              \
        }                                                                      \
    } while (0)

#define MMA_HALF(p) do {                                                       \
        _Pragma("unroll")                                                      \
        for (int mt = 0; mt < 4; mt++)                                         \
            _Pragma("unroll")                                                  \
            for (int nt = 0; nt < 8; nt++)                                     \
                mma16816(acc[mt][nt], fa[p][mt][0], fa[p][mt][1],              \
                         fa[p][mt][2], fa[p][mt][3],                           \
                         fb[p][nt][0], fb[p][nt][1]);                          \
    } while (0)

    int rslot = 0;   // kb % 3
    int wslot = 2;   // (kb+2) % 3
    for (int kb = 0; kb < NKB; kb++) {
        if (kb < NKB - 1) CP_WAIT(1);
        else              CP_WAIT(0);
        __syncthreads();

        if (kb + 2 < NKB) {
            load_stage(sb, wslot, kb + 2, m0, n0, tid);
            CP_COMMIT();
        }

        const uint32_t base = sb + rslot * STAGEB;
        // 4 k16-halves, LDSM of next half overlapped with MMAs of current
        LD_FRAGS(0, base, 0);
        LD_FRAGS(1, base, 32);
        MMA_HALF(0);
        LD_FRAGS(0, base, 64);
        MMA_HALF(1);
        LD_FRAGS(1, base, 96);
        MMA_HALF(0);
        MMA_HALF(1);

        rslot += 1; if (rslot == 3) rslot = 0;
        wslot += 1; if (wslot == 3) wslot = 0;
    }
    __syncthreads();   // SMEM now reusable for reduction

    // --------- fused epilogue: bias + row (max, sumexp) partials ------------
    float2 (*red)[2] = (float2(*)[2])(smem + OFF_RED);
#pragma unroll
    for (int mt = 0; mt < 4; mt++) {
#pragma unroll
        for (int half = 0; half < 2; half++) {
            const int rloc = wm * 64 + mt * 16 + g + half * 8;
            float v[16];
            float vmax = -1e30f;
#pragma unroll
            for (int nt = 0; nt < 8; nt++) {
                const int c0g = n0 + wn * 64 + nt * 8 + tig * 2;
                float v0 = acc[mt][nt][half * 2 + 0] + bias[c0g];
                float v1 = acc[mt][nt][half * 2 + 1] + bias[c0g + 1];
                v[nt * 2]     = v0;
                v[nt * 2 + 1] = v1;
                vmax = fmaxf(vmax, fmaxf(v0, v1));
            }
            float vsum = 0.f;
#pragma unroll
            for (int jj = 0; jj < 16; jj++) vsum += __expf(v[jj] - vmax);
#pragma unroll
            for (int off = 1; off < 4; off <<= 1) {
                float om = __shfl_xor_sync(0xffffffffu, vmax, off);
                float os = __shfl_xor_sync(0xffffffffu, vsum, off);
                float nm = fmaxf(vmax, om);
                vsum = vsum * __expf(vmax - nm) + os * __expf(om - nm);
                vmax = nm;
            }
            if (tig == 0) red[rloc][wn] = make_float2(vmax, vsum);
        }
    }
    __syncthreads();
    if (tid < 128) {
        float m = -1e30f, s = 0.f;
#pragma unroll
        for (int w = 0; w < 2; w++) {
            float2 p = red[tid][w];
            float nm = fmaxf(m, p.x);
            s = s * __expf(m - nm) + p.y * __expf(p.x - nm);
            m = nm;
        }
        const size_t idx = (size_t)(m0 + tid) * NP + blockIdx.y;
        g_pmax[idx] = m;
        g_psum[idx] = s;
    }
}

// ---------------- combine partials -> per-token logp ------------------------
__global__ void lse_kernel(const int* __restrict__ target) {
    const int row  = blockIdx.x * 8 + (threadIdx.x >> 5);
    const int lane = threadIdx.x & 31;
    const float* pm = g_pmax + (size_t)row * NP;
    const float* ps = g_psum + (size_t)row * NP;
    float m = -1e30f, s = 0.f;
    for (int j = lane; j < NP; j += 32) {
        float om = pm[j], os = ps[j];
        float nm = fmaxf(m, om);
        s = s * __expf(m - nm) + os * __expf(om - nm);
        m = nm;
    }
#pragma unroll
    for (int off = 16; off; off >>= 1) {
        float om = __shfl_xor_sync(0xffffffffu, m, off);
        float os = __shfl_xor_sync(0xffffffffu, s, off);
        float nm = fmaxf(m, om);
        s = s * __expf(m - nm) + os * __expf(om - nm);
        m = nm;
    }
    if (lane == 0) {
        const float lse = m + logf(s);
        const int t = target[row];
        g_ptok[row] = (t != IGNORE_INDEX) ? (g_tgt[row] - lse) : 0.f;
    }
}

// ---------------- final scalar loss -----------------------------------------
__global__ void final_kernel(const int* __restrict__ target,
                             const float* __restrict__ ref_c,
                             const float* __restrict__ ref_r,
                             float* __restrict__ out) {
    __shared__ float ssum[8];
    __shared__ float scnt[8];
    const int warp = threadIdx.x >> 5;
    const int lane = threadIdx.x & 31;
    float s = 0.f, c = 0.f;
    for (int t = lane; t < SEQ; t += 32) {
        const int row = warp * SEQ + t;
        if (target[row] != IGNORE_INDEX) {
            s += g_ptok[row];
            c += 1.f;
        }
    }
#pragma unroll
    for (int off = 16; off; off >>= 1) {
        s += __shfl_xor_sync(0xffffffffu, s, off);
        c += __shfl_xor_sync(0xffffffffu, c, off);
    }
    if (lane == 0) { ssum[warp] = s; scnt[warp] = c; }
    __syncthreads();
    if (threadIdx.x == 0) {
        float nll_num = 0.f, nll_den = 0.f;
        for (int b = 0; b < 4; b++) { nll_num += ssum[b]; nll_den += scnt[b]; }
        const float nll = -nll_num / nll_den;
        float pl = 0.f;
        for (int i = 0; i < 4; i++) {
            const float ca = ssum[i] / scnt[i] - ref_c[i];
            const float ra = ssum[4 + i] / scnt[4 + i] - ref_r[i];
            const float x  = 0.1f * (ca - ra);
            const float ls = fminf(x, 0.f) - log1pf(expf(-fabsf(x)));
            pl -= ls;
        }
        pl *= 0.25f;
        out[0] = pl + nll;
    }
}

// ---------------- launcher ---------------------------------------------------
extern "C" void kernel_launch(void* const* d_in, const int* in_sizes, int n_in,
                              void* d_out, int out_size) {
    const float* lin_w = (const float*)d_in[0];
    const float* x     = (const float*)d_in[1];
    const int*   tgt   = (const int*)d_in[2];
    const float* ref_c = (const float*)d_in[3];
    const float* ref_r = (const float*)d_in[4];
    const float* bias  = (const float*)d_in[5];
    float* out = (float*)d_out;

    cudaFuncSetAttribute(gemm_lse_kernel,
                         cudaFuncAttributeMaxDynamicSharedMemorySize, SMEM_BYTES);

    __nv_bfloat162* dW;
    __nv_bfloat162* dX;
    cudaGetSymbolAddress((void**)&dW, g_W);
    cudaGetSymbolAddress((void**)&dX, g_X);

    conv_kernel<<<2048, 256>>>((const float4*)lin_w, dW, VOCAB * HIDDEN / 4);
    conv_kernel<<<512, 256>>>((const float4*)x, dX, NTOK * HIDDEN / 4);

    tgt_kernel<<<NTOK / 8, 256>>>(x, lin_w, bias, tgt);

    dim3 grid(NTOK / 128, NP);   // m fast-varying -> B panel shared in-wave
    gemm_lse_kernel<<<grid, 128, SMEM_BYTES>>>(bias);

    lse_kernel<<<NTOK / 8, 256>>>(tgt);
    final_kernel<<<1, 256>>>(tgt, ref_c, ref_r, out);
}

// round 10
// speedup vs baseline: 1.0594x; 1.0002x over previous
#include <cuda_runtime.h>
#include <cuda_bf16.h>
#include <cstdint>

#define VOCAB  32000
#define HIDDEN 4096
#define NTOK   4096      // 8*512 tokens
#define SEQ    512
#define NP     250       // VOCAB / 128 partial tiles per row
#define IGNORE_INDEX (-100)

#define BK     64                // bf16 per K block (128 bytes)
#define NKB    (HIDDEN / BK)     // 64
#define NSTAGE 3
#define ROWB   144               // 128B row + 16B pad (conflict-free LDSM)
#define ABYTES (128 * ROWB)      // 18432 per operand per stage
#define STAGEB (2 * ABYTES)      // 36864 (A then B)
#define OFF_RED (NSTAGE * STAGEB)            // 110592
#define SMEM_BYTES (OFF_RED + 128 * 2 * 8)   // + red[128][2] float2 = 112640

// ---------------- scratch (device globals; no allocation allowed) ----------
__device__ __align__(128) __nv_bfloat16 g_W[(size_t)VOCAB * HIDDEN];  // 262 MB
__device__ __align__(128) __nv_bfloat16 g_X[(size_t)NTOK * HIDDEN];   // 33 MB
__device__ float g_pmax[(size_t)NTOK * NP];
__device__ float g_psum[(size_t)NTOK * NP];
__device__ float g_tgt[NTOK];
__device__ float g_ptok[NTOK];

// ---------------- small asm helpers ----------------------------------------
__device__ __forceinline__ uint32_t smem_u32(const void* p) {
    uint32_t a;
    asm("{ .reg .u64 t; cvta.to.shared.u64 t, %1; cvt.u32.u64 %0, t; }"
        : "=r"(a) : "l"(p));
    return a;
}
#define CP_ASYNC16(dst, src) \
    asm volatile("cp.async.cg.shared.global [%0], [%1], 16;" :: "r"(dst), "l"(src))
#define CP_COMMIT() asm volatile("cp.async.commit_group;" ::: "memory")
#define CP_WAIT(n)  asm volatile("cp.async.wait_group %0;" :: "n"(n) : "memory")

#define LDMATRIX_X4(r0, r1, r2, r3, addr) \
    asm volatile("ldmatrix.sync.aligned.m8n8.x4.shared.b16 {%0,%1,%2,%3}, [%4];" \
                 : "=r"(r0), "=r"(r1), "=r"(r2), "=r"(r3) : "r"(addr))

__device__ __forceinline__ void mma16816(float c[4],
                                         uint32_t a0, uint32_t a1, uint32_t a2, uint32_t a3,
                                         uint32_t b0, uint32_t b1) {
    asm volatile(
        "mma.sync.aligned.m16n8k16.row.col.f32.bf16.bf16.f32 "
        "{%0,%1,%2,%3}, {%4,%5,%6,%7}, {%8,%9}, {%0,%1,%2,%3};\n"
        : "+f"(c[0]), "+f"(c[1]), "+f"(c[2]), "+f"(c[3])
        : "r"(a0), "r"(a1), "r"(a2), "r"(a3), "r"(b0), "r"(b1));
}

// ---------------- fp32 -> bf16 conversion ----------------------------------
__global__ void conv_kernel(const float4* __restrict__ src,
                            __nv_bfloat162* __restrict__ dst, int n4) {
    for (int i = blockIdx.x * blockDim.x + threadIdx.x; i < n4;
         i += gridDim.x * blockDim.x) {
        float4 v = src[i];
        dst[2 * i]     = __floats2bfloat162_rn(v.x, v.y);
        dst[2 * i + 1] = __floats2bfloat162_rn(v.z, v.w);
    }
}

// ---------------- exact fp32 target logits ----------------------------------
__global__ void tgt_kernel(const float* __restrict__ x,
                           const float* __restrict__ w,
                           const float* __restrict__ bias,
                           const int* __restrict__ target) {
    const int row  = blockIdx.x * 8 + (threadIdx.x >> 5);
    const int lane = threadIdx.x & 31;
    const int t = target[row];
    if (t == IGNORE_INDEX) {
        if (lane == 0) g_tgt[row] = 0.f;
        return;
    }
    const float4* xr = reinterpret_cast<const float4*>(x + (size_t)row * HIDDEN);
    const float4* wr = reinterpret_cast<const float4*>(w + (size_t)t * HIDDEN);
    float s = 0.f;
#pragma unroll 4
    for (int j = lane; j < HIDDEN / 4; j += 32) {
        float4 a = xr[j];
        float4 b = wr[j];
        s += a.x * b.x + a.y * b.y + a.z * b.z + a.w * b.w;
    }
#pragma unroll
    for (int off = 16; off; off >>= 1)
        s += __shfl_xor_sync(0xffffffffu, s, off);
    if (lane == 0) g_tgt[row] = s + bias[t];
}

// ---------------- stage loader: cp.async GMEM bf16 -> padded SMEM -----------
// 128 threads: rows of 128B = 8 chunks; 1024 chunks per operand -> 8/thread.
__device__ __forceinline__ void load_stage(uint32_t sb, int slot, int kb,
                                           int m0, int n0, int tid) {
    const uint32_t base = sb + slot * STAGEB;
#pragma unroll
    for (int h = 0; h < 8; h++) {
        const int c   = tid + h * 128;
        const int row = c >> 3;
        const int seg = c & 7;
        const uint32_t dA = base + row * ROWB + seg * 16;
        const __nv_bfloat16* sA = g_X + (size_t)(m0 + row) * HIDDEN + kb * BK + seg * 8;
        CP_ASYNC16(dA, sA);
        const uint32_t dB = base + ABYTES + row * ROWB + seg * 16;
        const __nv_bfloat16* sB = g_W + (size_t)(n0 + row) * HIDDEN + kb * BK + seg * 8;
        CP_ASYNC16(dB, sB);
    }
}

// ---------------- bf16 GEMM (ldmatrix + mma.16816) + fused LSE --------------
// Grid (32 m-tiles [fast], 250 n-tiles). 128 threads, 4 warps (2x2).
// CTA tile 128x128, warp tile 64x64, BK=64, 3-stage ring (prefetch dist 2),
// plain compiler-scheduled inner loop (LDSM burst -> MMA burst per k16-half).
__global__ __launch_bounds__(128, 2)
void gemm_lse_kernel(const float* __restrict__ bias) {
    extern __shared__ char smem[];
    const uint32_t sb = smem_u32(smem);

    const int tid  = threadIdx.x;
    const int lane = tid & 31;
    const int warp = tid >> 5;
    const int g    = lane >> 2;     // 0..7
    const int tig  = lane & 3;      // 0..3
    const int wm   = warp >> 1;     // 0..1 : rows wm*64..+63
    const int wn   = warp & 1;      // 0..1 : cols wn*64..+63
    const int m0   = blockIdx.x * 128;
    const int n0   = blockIdx.y * 128;

    float acc[4][8][4];
#pragma unroll
    for (int i = 0; i < 4; i++)
#pragma unroll
        for (int j = 0; j < 8; j++)
#pragma unroll
            for (int k = 0; k < 4; k++) acc[i][j][k] = 0.f;

    // prologue: stages 0,1 in flight (slots 0,1)
    load_stage(sb, 0, 0, m0, n0, tid); CP_COMMIT();
    load_stage(sb, 1, 1, m0, n0, tid); CP_COMMIT();

    // ldmatrix per-thread byte offsets (constant across stages)
    const int a_row  = lane & 15;
    const int a_col8 = (lane >> 4) & 1;
    const int b_n    = ((lane >> 4) & 1) * 8 + (lane & 7);
    const int b_k8   = (lane >> 3) & 1;
    uint32_t offA[4], offB[4];
#pragma unroll
    for (int mt = 0; mt < 4; mt++)
        offA[mt] = (wm * 64 + mt * 16 + a_row) * ROWB + a_col8 * 16;
#pragma unroll
    for (int np = 0; np < 4; np++)
        offB[np] = ABYTES + (wn * 64 + np * 16 + b_n) * ROWB + b_k8 * 16;

    int rslot = 0;   // kb % 3
    int wslot = 2;   // (kb+2) % 3
    for (int kb = 0; kb < NKB; kb++) {
        if (kb < NKB - 1) CP_WAIT(1);
        else              CP_WAIT(0);
        __syncthreads();

        if (kb + 2 < NKB) {
            load_stage(sb, wslot, kb + 2, m0, n0, tid);
            CP_COMMIT();
        }

        const uint32_t base = sb + rslot * STAGEB;
#pragma unroll
        for (int kh = 0; kh < 4; kh++) {          // 4 k16-halves per 128B row
            const uint32_t hb = base + kh * 32;
            uint32_t a[4][4], b[8][2];
#pragma unroll
            for (int mt = 0; mt < 4; mt++)
                LDMATRIX_X4(a[mt][0], a[mt][1], a[mt][2], a[mt][3],
                            hb + offA[mt]);
#pragma unroll
            for (int np = 0; np < 4; np++) {
                uint32_t r0, r1, r2, r3;
                LDMATRIX_X4(r0, r1, r2, r3, hb + offB[np]);
                b[np * 2][0] = r0;     b[np * 2][1] = r1;
                b[np * 2 + 1][0] = r2; b[np * 2 + 1][1] = r3;
            }
#pragma unroll
            for (int mt = 0; mt < 4; mt++)
#pragma unroll
                for (int nt = 0; nt < 8; nt++)
                    mma16816(acc[mt][nt], a[mt][0], a[mt][1], a[mt][2], a[mt][3],
                             b[nt][0], b[nt][1]);
        }

        rslot += 1; if (rslot == 3) rslot = 0;
        wslot += 1; if (wslot == 3) wslot = 0;
    }
    __syncthreads();   // SMEM now reusable for reduction

    // --------- fused epilogue: bias + row (max, sumexp) partials ------------
    float2 (*red)[2] = (float2(*)[2])(smem + OFF_RED);
#pragma unroll
    for (int mt = 0; mt < 4; mt++) {
#pragma unroll
        for (int half = 0; half < 2; half++) {
            const int rloc = wm * 64 + mt * 16 + g + half * 8;
            float v[16];
            float vmax = -1e30f;
#pragma unroll
            for (int nt = 0; nt < 8; nt++) {
                const int c0g = n0 + wn * 64 + nt * 8 + tig * 2;
                float v0 = acc[mt][nt][half * 2 + 0] + bias[c0g];
                float v1 = acc[mt][nt][half * 2 + 1] + bias[c0g + 1];
                v[nt * 2]     = v0;
                v[nt * 2 + 1] = v1;
                vmax = fmaxf(vmax, fmaxf(v0, v1));
            }
            float vsum = 0.f;
#pragma unroll
            for (int jj = 0; jj < 16; jj++) vsum += __expf(v[jj] - vmax);
#pragma unroll
            for (int off = 1; off < 4; off <<= 1) {
                float om = __shfl_xor_sync(0xffffffffu, vmax, off);
                float os = __shfl_xor_sync(0xffffffffu, vsum, off);
                float nm = fmaxf(vmax, om);
                vsum = vsum * __expf(vmax - nm) + os * __expf(om - nm);
                vmax = nm;
            }
            if (tig == 0) red[rloc][wn] = make_float2(vmax, vsum);
        }
    }
    __syncthreads();
    if (tid < 128) {
        float m = -1e30f, s = 0.f;
#pragma unroll
        for (int w = 0; w < 2; w++) {
            float2 p = red[tid][w];
            float nm = fmaxf(m, p.x);
            s = s * __expf(m - nm) + p.y * __expf(p.x - nm);
            m = nm;
        }
        const size_t idx = (size_t)(m0 + tid) * NP + blockIdx.y;
        g_pmax[idx] = m;
        g_psum[idx] = s;
    }
}

// ---------------- combine partials -> per-token logp ------------------------
__global__ void lse_kernel(const int* __restrict__ target) {
    const int row  = blockIdx.x * 8 + (threadIdx.x >> 5);
    const int lane = threadIdx.x & 31;
    const float* pm = g_pmax + (size_t)row * NP;
    const float* ps = g_psum + (size_t)row * NP;
    float m = -1e30f, s = 0.f;
    for (int j = lane; j < NP; j += 32) {
        float om = pm[j], os = ps[j];
        float nm = fmaxf(m, om);
        s = s * __expf(m - nm) + os * __expf(om - nm);
        m = nm;
    }
#pragma unroll
    for (int off = 16; off; off >>= 1) {
        float om = __shfl_xor_sync(0xffffffffu, m, off);
        float os = __shfl_xor_sync(0xffffffffu, s, off);
        float nm = fmaxf(m, om);
        s = s * __expf(m - nm) + os * __expf(om - nm);
        m = nm;
    }
    if (lane == 0) {
        const float lse = m + logf(s);
        const int t = target[row];
        g_ptok[row] = (t != IGNORE_INDEX) ? (g_tgt[row] - lse) : 0.f;
    }
}

// ---------------- final scalar loss -----------------------------------------
__global__ void final_kernel(const int* __restrict__ target,
                             const float* __restrict__ ref_c,
                             const float* __restrict__ ref_r,
                             float* __restrict__ out) {
    __shared__ float ssum[8];
    __shared__ float scnt[8];
    const int warp = threadIdx.x >> 5;
    const int lane = threadIdx.x & 31;
    float s = 0.f, c = 0.f;
    for (int t = lane; t < SEQ; t += 32) {
        const int row = warp * SEQ + t;
        if (target[row] != IGNORE_INDEX) {
            s += g_ptok[row];
            c += 1.f;
        }
    }
#pragma unroll
    for (int off = 16; off; off >>= 1) {
        s += __shfl_xor_sync(0xffffffffu, s, off);
        c += __shfl_xor_sync(0xffffffffu, c, off);
    }
    if (lane == 0) { ssum[warp] = s; scnt[warp] = c; }
    __syncthreads();
    if (threadIdx.x == 0) {
        float nll_num = 0.f, nll_den = 0.f;
        for (int b = 0; b < 4; b++) { nll_num += ssum[b]; nll_den += scnt[b]; }
        const float nll = -nll_num / nll_den;
        float pl = 0.f;
        for (int i = 0; i < 4; i++) {
            const float ca = ssum[i] / scnt[i] - ref_c[i];
            const float ra = ssum[4 + i] / scnt[4 + i] - ref_r[i];
            const float x  = 0.1f * (ca - ra);
            const float ls = fminf(x, 0.f) - log1pf(expf(-fabsf(x)));
            pl -= ls;
        }
        pl *= 0.25f;
        out[0] = pl + nll;
    }
}

// ---------------- launcher ---------------------------------------------------
extern "C" void kernel_launch(void* const* d_in, const int* in_sizes, int n_in,
                              void* d_out, int out_size) {
    const float* lin_w = (const float*)d_in[0];
    const float* x     = (const float*)d_in[1];
    const int*   tgt   = (const int*)d_in[2];
    const float* ref_c = (const float*)d_in[3];
    const float* ref_r = (const float*)d_in[4];
    const float* bias  = (const float*)d_in[5];
    float* out = (float*)d_out;

    cudaFuncSetAttribute(gemm_lse_kernel,
                         cudaFuncAttributeMaxDynamicSharedMemorySize, SMEM_BYTES);

    __nv_bfloat162* dW;
    __nv_bfloat162* dX;
    cudaGetSymbolAddress((void**)&dW, g_W);
    cudaGetSymbolAddress((void**)&dX, g_X);

    conv_kernel<<<2048, 256>>>((const float4*)lin_w, dW, VOCAB * HIDDEN / 4);
    conv_kernel<<<512, 256>>>((const float4*)x, dX, NTOK * HIDDEN / 4);

    tgt_kernel<<<NTOK / 8, 256>>>(x, lin_w, bias, tgt);

    dim3 grid(NTOK / 128, NP);   // m fast-varying -> B panel shared in-wave
    gemm_lse_kernel<<<grid, 128, SMEM_BYTES>>>(bias);

    lse_kernel<<<NTOK / 8, 256>>>(tgt);
    final_kernel<<<1, 256>>>(tgt, ref_c, ref_r, out);
}

// round 11
// speedup vs baseline: 1.1547x; 1.0899x over previous
#include <cuda_runtime.h>
#include <cuda_bf16.h>
#include <cstdint>

#define VOCAB  32000
#define HIDDEN 4096
#define NTOK   4096      // 8*512 tokens
#define SEQ    512
#define NP     250       // VOCAB / 128 partial tiles per row
#define IGNORE_INDEX (-100)

#define BK     32                // bf16 per K block
#define NKB    (HIDDEN / BK)     // 128
#define NSTAGE 5
#define ROWB   80                // padded row stride in bytes (40 bf16)
#define ABYTES (128 * ROWB)      // 10240 per operand per stage
#define STAGEB (2 * ABYTES)      // 20480 (A then B)
#define OFF_RED (NSTAGE * STAGEB)            // 102400
#define SMEM_BYTES (OFF_RED + 128 * 2 * 8)   // + red[128][2] float2 = 104448

// ---------------- scratch (device globals; no allocation allowed) ----------
__device__ __align__(128) __nv_bfloat16 g_W[(size_t)VOCAB * HIDDEN];  // 262 MB
__device__ __align__(128) __nv_bfloat16 g_X[(size_t)NTOK * HIDDEN];   // 33 MB
__device__ float g_pmax[(size_t)NTOK * NP];
__device__ float g_psum[(size_t)NTOK * NP];
__device__ float g_tgt[NTOK];
__device__ float g_ptok[NTOK];

// ---------------- small asm helpers ----------------------------------------
__device__ __forceinline__ uint32_t smem_u32(const void* p) {
    uint32_t a;
    asm("{ .reg .u64 t; cvta.to.shared.u64 t, %1; cvt.u32.u64 %0, t; }"
        : "=r"(a) : "l"(p));
    return a;
}
#define CP_ASYNC16(dst, src) \
    asm volatile("cp.async.cg.shared.global [%0], [%1], 16;" :: "r"(dst), "l"(src))
#define CP_COMMIT() asm volatile("cp.async.commit_group;" ::: "memory")
#define CP_WAIT(n)  asm volatile("cp.async.wait_group %0;" :: "n"(n) : "memory")

#define LDMATRIX_X4(r0, r1, r2, r3, addr) \
    asm volatile("ldmatrix.sync.aligned.m8n8.x4.shared.b16 {%0,%1,%2,%3}, [%4];" \
                 : "=r"(r0), "=r"(r1), "=r"(r2), "=r"(r3) : "r"(addr))

__device__ __forceinline__ void mma16816(float c[4],
                                         uint32_t a0, uint32_t a1, uint32_t a2, uint32_t a3,
                                         uint32_t b0, uint32_t b1) {
    asm volatile(
        "mma.sync.aligned.m16n8k16.row.col.f32.bf16.bf16.f32 "
        "{%0,%1,%2,%3}, {%4,%5,%6,%7}, {%8,%9}, {%0,%1,%2,%3};\n"
        : "+f"(c[0]), "+f"(c[1]), "+f"(c[2]), "+f"(c[3])
        : "r"(a0), "r"(a1), "r"(a2), "r"(a3), "r"(b0), "r"(b1));
}

// ---------------- fp32 -> bf16 conversion ----------------------------------
__global__ void conv_kernel(const float4* __restrict__ src,
                            __nv_bfloat162* __restrict__ dst, int n4) {
    for (int i = blockIdx.x * blockDim.x + threadIdx.x; i < n4;
         i += gridDim.x * blockDim.x) {
        float4 v = src[i];
        dst[2 * i]     = __floats2bfloat162_rn(v.x, v.y);
        dst[2 * i + 1] = __floats2bfloat162_rn(v.z, v.w);
    }
}

// ---------------- exact fp32 target logits ----------------------------------
__global__ void tgt_kernel(const float* __restrict__ x,
                           const float* __restrict__ w,
                           const float* __restrict__ bias,
                           const int* __restrict__ target) {
    const int row  = blockIdx.x * 8 + (threadIdx.x >> 5);
    const int lane = threadIdx.x & 31;
    const int t = target[row];
    if (t == IGNORE_INDEX) {
        if (lane == 0) g_tgt[row] = 0.f;
        return;
    }
    const float4* xr = reinterpret_cast<const float4*>(x + (size_t)row * HIDDEN);
    const float4* wr = reinterpret_cast<const float4*>(w + (size_t)t * HIDDEN);
    float s = 0.f;
#pragma unroll 4
    for (int j = lane; j < HIDDEN / 4; j += 32) {
        float4 a = xr[j];
        float4 b = wr[j];
        s += a.x * b.x + a.y * b.y + a.z * b.z + a.w * b.w;
    }
#pragma unroll
    for (int off = 16; off; off >>= 1)
        s += __shfl_xor_sync(0xffffffffu, s, off);
    if (lane == 0) g_tgt[row] = s + bias[t];
}

// ---------------- stage loader: cp.async GMEM bf16 -> padded SMEM -----------
// 128 threads: 512 16B chunks per operand per stage -> 4 per thread each.
__device__ __forceinline__ void load_stage(uint32_t sb, int slot, int kb,
                                           int m0, int n0, int tid) {
    const uint32_t base = sb + slot * STAGEB;
#pragma unroll
    for (int h = 0; h < 4; h++) {
        const int c   = tid + h * 128;
        const int row = c >> 2;
        const int seg = c & 3;
        const uint32_t dA = base + row * ROWB + seg * 16;
        const __nv_bfloat16* sA = g_X + (size_t)(m0 + row) * HIDDEN + kb * BK + seg * 8;
        CP_ASYNC16(dA, sA);
        const uint32_t dB = base + ABYTES + row * ROWB + seg * 16;
        const __nv_bfloat16* sB = g_W + (size_t)(n0 + row) * HIDDEN + kb * BK + seg * 8;
        CP_ASYNC16(dB, sB);
    }
}

// ---------------- bf16 GEMM (ldmatrix + mma.16816) + fused LSE --------------
// Grid (32 m-tiles [fast], 250 n-tiles). 128 threads, 4 warps (2x2).
// CTA tile 128x128, warp tile 64x64, BK=32, 5-stage cp.async pipeline
// (prefetch distance 4), compiler-scheduled inner loop (R6 structure).
__global__ __launch_bounds__(128, 2)
void gemm_lse_kernel(const float* __restrict__ bias) {
    extern __shared__ char smem[];
    const uint32_t sb = smem_u32(smem);

    const int tid  = threadIdx.x;
    const int lane = tid & 31;
    const int warp = tid >> 5;
    const int g    = lane >> 2;     // 0..7
    const int tig  = lane & 3;      // 0..3
    const int wm   = warp >> 1;     // 0..1 : rows wm*64..+63
    const int wn   = warp & 1;      // 0..1 : cols wn*64..+63
    const int m0   = blockIdx.x * 128;
    const int n0   = blockIdx.y * 128;

    float acc[4][8][4];
#pragma unroll
    for (int i = 0; i < 4; i++)
#pragma unroll
        for (int j = 0; j < 8; j++)
#pragma unroll
            for (int k = 0; k < 4; k++) acc[i][j][k] = 0.f;

    // prologue: 4 stages in flight (slots 0..3)
    load_stage(sb, 0, 0, m0, n0, tid); CP_COMMIT();
    load_stage(sb, 1, 1, m0, n0, tid); CP_COMMIT();
    load_stage(sb, 2, 2, m0, n0, tid); CP_COMMIT();
    load_stage(sb, 3, 3, m0, n0, tid); CP_COMMIT();

    // ldmatrix lane addressing (constant across stages)
    const int a_row  = lane & 15;
    const int a_col8 = (lane >> 4) & 1;
    const int b_n    = ((lane >> 4) & 1) * 8 + (lane & 7);
    const int b_k8   = (lane >> 3) & 1;
    uint32_t offA[4], offB[4];
#pragma unroll
    for (int mt = 0; mt < 4; mt++)
        offA[mt] = (wm * 64 + mt * 16 + a_row) * ROWB + a_col8 * 16;
#pragma unroll
    for (int np = 0; np < 4; np++)
        offB[np] = ABYTES + (wn * 64 + np * 16 + b_n) * ROWB + b_k8 * 16;

    int rslot = 0;   // kb % 5
    int wslot = 4;   // (kb+4) % 5
    for (int kb = 0; kb < NKB; kb++) {
        const int rem = NKB - 1 - kb;
        if (rem >= 3)      CP_WAIT(3);
        else if (rem == 2) CP_WAIT(2);
        else if (rem == 1) CP_WAIT(1);
        else               CP_WAIT(0);
        __syncthreads();

        if (kb + 4 < NKB) {
            load_stage(sb, wslot, kb + 4, m0, n0, tid);
            CP_COMMIT();
        }

        const uint32_t base = sb + rslot * STAGEB;
#pragma unroll
        for (int kh = 0; kh < 2; kh++) {
            const uint32_t hb = base + kh * 32;
            uint32_t a[4][4], b[8][2];
#pragma unroll
            for (int mt = 0; mt < 4; mt++)
                LDMATRIX_X4(a[mt][0], a[mt][1], a[mt][2], a[mt][3],
                            hb + offA[mt]);
#pragma unroll
            for (int np = 0; np < 4; np++) {
                uint32_t r0, r1, r2, r3;
                LDMATRIX_X4(r0, r1, r2, r3, hb + offB[np]);
                b[np * 2][0] = r0;     b[np * 2][1] = r1;
                b[np * 2 + 1][0] = r2; b[np * 2 + 1][1] = r3;
            }
#pragma unroll
            for (int mt = 0; mt < 4; mt++)
#pragma unroll
                for (int nt = 0; nt < 8; nt++)
                    mma16816(acc[mt][nt], a[mt][0], a[mt][1], a[mt][2], a[mt][3],
                             b[nt][0], b[nt][1]);
        }

        rslot += 1; if (rslot == NSTAGE) rslot = 0;
        wslot += 1; if (wslot == NSTAGE) wslot = 0;
    }
    __syncthreads();   // SMEM now reusable for reduction

    // --------- fused epilogue: bias + row (max, sumexp) partials ------------
    float2 (*red)[2] = (float2(*)[2])(smem + OFF_RED);
#pragma unroll
    for (int mt = 0; mt < 4; mt++) {
#pragma unroll
        for (int half = 0; half < 2; half++) {
            const int rloc = wm * 64 + mt * 16 + g + half * 8;
            float v[16];
            float vmax = -1e30f;
#pragma unroll
            for (int nt = 0; nt < 8; nt++) {
                const int c0g = n0 + wn * 64 + nt * 8 + tig * 2;
                float v0 = acc[mt][nt][half * 2 + 0] + bias[c0g];
                float v1 = acc[mt][nt][half * 2 + 1] + bias[c0g + 1];
                v[nt * 2]     = v0;
                v[nt * 2 + 1] = v1;
                vmax = fmaxf(vmax, fmaxf(v0, v1));
            }
            float vsum = 0.f;
#pragma unroll
            for (int jj = 0; jj < 16; jj++) vsum += __expf(v[jj] - vmax);
#pragma unroll
            for (int off = 1; off < 4; off <<= 1) {
                float om = __shfl_xor_sync(0xffffffffu, vmax, off);
                float os = __shfl_xor_sync(0xffffffffu, vsum, off);
                float nm = fmaxf(vmax, om);
                vsum = vsum * __expf(vmax - nm) + os * __expf(om - nm);
                vmax = nm;
            }
            if (tig == 0) red[rloc][wn] = make_float2(vmax, vsum);
        }
    }
    __syncthreads();
    if (tid < 128) {
        float m = -1e30f, s = 0.f;
#pragma unroll
        for (int w = 0; w < 2; w++) {
            float2 p = red[tid][w];
            float nm = fmaxf(m, p.x);
            s = s * __expf(m - nm) + p.y * __expf(p.x - nm);
            m = nm;
        }
        const size_t idx = (size_t)(m0 + tid) * NP + blockIdx.y;
        g_pmax[idx] = m;
        g_psum[idx] = s;
    }
}

// ---------------- combine partials -> per-token logp ------------------------
__global__ void lse_kernel(const int* __restrict__ target) {
    const int row  = blockIdx.x * 8 + (threadIdx.x >> 5);
    const int lane = threadIdx.x & 31;
    const float* pm = g_pmax + (size_t)row * NP;
    const float* ps = g_psum + (size_t)row * NP;
    float m = -1e30f, s = 0.f;
    for (int j = lane; j < NP; j += 32) {
        float om = pm[j], os = ps[j];
        float nm = fmaxf(m, om);
        s = s * __expf(m - nm) + os * __expf(om - nm);
        m = nm;
    }
#pragma unroll
    for (int off = 16; off; off >>= 1) {
        float om = __shfl_xor_sync(0xffffffffu, m, off);
        float os = __shfl_xor_sync(0xffffffffu, s, off);
        float nm = fmaxf(m, om);
        s = s * __expf(m - nm) + os * __expf(om - nm);
        m = nm;
    }
    if (lane == 0) {
        const float lse = m + logf(s);
        const int t = target[row];
        g_ptok[row] = (t != IGNORE_INDEX) ? (g_tgt[row] - lse) : 0.f;
    }
}

// ---------------- final scalar loss -----------------------------------------
__global__ void final_kernel(const int* __restrict__ target,
                             const float* __restrict__ ref_c,
                             const float* __restrict__ ref_r,
                             float* __restrict__ out) {
    __shared__ float ssum[8];
    __shared__ float scnt[8];
    const int warp = threadIdx.x >> 5;
    const int lane = threadIdx.x & 31;
    float s = 0.f, c = 0.f;
    for (int t = lane; t < SEQ; t += 32) {
        const int row = warp * SEQ + t;
        if (target[row] != IGNORE_INDEX) {
            s += g_ptok[row];
            c += 1.f;
        }
    }
#pragma unroll
    for (int off = 16; off; off >>= 1) {
        s += __shfl_xor_sync(0xffffffffu, s, off);
        c += __shfl_xor_sync(0xffffffffu, c, off);
    }
    if (lane == 0) { ssum[warp] = s; scnt[warp] = c; }
    __syncthreads();
    if (threadIdx.x == 0) {
        float nll_num = 0.f, nll_den = 0.f;
        for (int b = 0; b < 4; b++) { nll_num += ssum[b]; nll_den += scnt[b]; }
        const float nll = -nll_num / nll_den;
        float pl = 0.f;
        for (int i = 0; i < 4; i++) {
            const float ca = ssum[i] / scnt[i] - ref_c[i];
            const float ra = ssum[4 + i] / scnt[4 + i] - ref_r[i];
            const float x  = 0.1f * (ca - ra);
            const float ls = fminf(x, 0.f) - log1pf(expf(-fabsf(x)));
            pl -= ls;
        }
        pl *= 0.25f;
        out[0] = pl + nll;
    }
}

// ---------------- launcher ---------------------------------------------------
extern "C" void kernel_launch(void* const* d_in, const int* in_sizes, int n_in,
                              void* d_out, int out_size) {
    const float* lin_w = (const float*)d_in[0];
    const float* x     = (const float*)d_in[1];
    const int*   tgt   = (const int*)d_in[2];
    const float* ref_c = (const float*)d_in[3];
    const float* ref_r = (const float*)d_in[4];
    const float* bias  = (const float*)d_in[5];
    float* out = (float*)d_out;

    cudaFuncSetAttribute(gemm_lse_kernel,
                         cudaFuncAttributeMaxDynamicSharedMemorySize, SMEM_BYTES);

    __nv_bfloat162* dW;
    __nv_bfloat162* dX;
    cudaGetSymbolAddress((void**)&dW, g_W);
    cudaGetSymbolAddress((void**)&dX, g_X);

    conv_kernel<<<2048, 256>>>((const float4*)lin_w, dW, VOCAB * HIDDEN / 4);
    conv_kernel<<<512, 256>>>((const float4*)x, dX, NTOK * HIDDEN / 4);

    tgt_kernel<<<NTOK / 8, 256>>>(x, lin_w, bias, tgt);

    dim3 grid(NTOK / 128, NP);   // m fast-varying -> B panel shared in-wave
    gemm_lse_kernel<<<grid, 128, SMEM_BYTES>>>(bias);

    lse_kernel<<<NTOK / 8, 256>>>(tgt);
    final_kernel<<<1, 256>>>(tgt, ref_c, ref_r, out);
}

// round 12
// speedup vs baseline: 1.2006x; 1.0398x over previous
#include <cuda_runtime.h>
#include <cuda_bf16.h>
#include <cstdint>

#define VOCAB  32000
#define HIDDEN 4096
#define NTOK   4096      // 8*512 tokens
#define SEQ    512
#define NP     250       // VOCAB / 128 partial tiles per row
#define IGNORE_INDEX (-100)

#define BK     32                // bf16 per K block
#define NKB    (HIDDEN / BK)     // 128
#define NSTAGE 4
#define ROWB   80                // padded row stride in bytes (40 bf16)
#define ABYTES (128 * ROWB)      // 10240 per operand per stage
#define STAGEB (2 * ABYTES)      // 20480 (A then B)
#define OFF_RED (NSTAGE * STAGEB)            // 81920
#define SMEM_BYTES (OFF_RED + 128 * 2 * 8)   // + red[128][2] float2 = 83968

// ---------------- scratch (device globals; no allocation allowed) ----------
__device__ __align__(128) __nv_bfloat16 g_W[(size_t)VOCAB * HIDDEN];  // 262 MB
__device__ __align__(128) __nv_bfloat16 g_X[(size_t)NTOK * HIDDEN];   // 33 MB
__device__ float g_pmax[(size_t)NTOK * NP];
__device__ float g_psum[(size_t)NTOK * NP];
__device__ float g_tgt[NTOK];
__device__ float g_ptok[NTOK];

// ---------------- small asm helpers ----------------------------------------
__device__ __forceinline__ uint32_t smem_u32(const void* p) {
    uint32_t a;
    asm("{ .reg .u64 t; cvta.to.shared.u64 t, %1; cvt.u32.u64 %0, t; }"
        : "=r"(a) : "l"(p));
    return a;
}
#define CP_ASYNC16(dst, src) \
    asm volatile("cp.async.cg.shared.global [%0], [%1], 16;" :: "r"(dst), "l"(src))
#define CP_COMMIT() asm volatile("cp.async.commit_group;" ::: "memory")
#define CP_WAIT(n)  asm volatile("cp.async.wait_group %0;" :: "n"(n) : "memory")

#define LDMATRIX_X4(r0, r1, r2, r3, addr) \
    asm volatile("ldmatrix.sync.aligned.m8n8.x4.shared.b16 {%0,%1,%2,%3}, [%4];" \
                 : "=r"(r0), "=r"(r1), "=r"(r2), "=r"(r3) : "r"(addr))

__device__ __forceinline__ void mma16816(float c[4],
                                         uint32_t a0, uint32_t a1, uint32_t a2, uint32_t a3,
                                         uint32_t b0, uint32_t b1) {
    asm volatile(
        "mma.sync.aligned.m16n8k16.row.col.f32.bf16.bf16.f32 "
        "{%0,%1,%2,%3}, {%4,%5,%6,%7}, {%8,%9}, {%0,%1,%2,%3};\n"
        : "+f"(c[0]), "+f"(c[1]), "+f"(c[2]), "+f"(c[3])
        : "r"(a0), "r"(a1), "r"(a2), "r"(a3), "r"(b0), "r"(b1));
}

// ---------------- fp32 -> bf16 conversion ----------------------------------
__global__ void conv_kernel(const float4* __restrict__ src,
                            __nv_bfloat162* __restrict__ dst, int n4) {
    for (int i = blockIdx.x * blockDim.x + threadIdx.x; i < n4;
         i += gridDim.x * blockDim.x) {
        float4 v = src[i];
        dst[2 * i]     = __floats2bfloat162_rn(v.x, v.y);
        dst[2 * i + 1] = __floats2bfloat162_rn(v.z, v.w);
    }
}

// ---------------- exact fp32 target logits ----------------------------------
__global__ void tgt_kernel(const float* __restrict__ x,
                           const float* __restrict__ w,
                           const float* __restrict__ bias,
                           const int* __restrict__ target) {
    const int row  = blockIdx.x * 8 + (threadIdx.x >> 5);
    const int lane = threadIdx.x & 31;
    const int t = target[row];
    if (t == IGNORE_INDEX) {
        if (lane == 0) g_tgt[row] = 0.f;
        return;
    }
    const float4* xr = reinterpret_cast<const float4*>(x + (size_t)row * HIDDEN);
    const float4* wr = reinterpret_cast<const float4*>(w + (size_t)t * HIDDEN);
    float s = 0.f;
#pragma unroll 4
    for (int j = lane; j < HIDDEN / 4; j += 32) {
        float4 a = xr[j];
        float4 b = wr[j];
        s += a.x * b.x + a.y * b.y + a.z * b.z + a.w * b.w;
    }
#pragma unroll
    for (int off = 16; off; off >>= 1)
        s += __shfl_xor_sync(0xffffffffu, s, off);
    if (lane == 0) g_tgt[row] = s + bias[t];
}

// ---------------- stage loader: cp.async GMEM bf16 -> padded SMEM -----------
// 128 threads: 512 16B chunks per operand per stage -> 4 per thread each.
__device__ __forceinline__ void load_stage(uint32_t sb, int stage, int kb,
                                           int m0, int n0, int tid) {
    const uint32_t base = sb + stage * STAGEB;
#pragma unroll
    for (int h = 0; h < 4; h++) {
        const int c   = tid + h * 128;
        const int row = c >> 2;
        const int seg = c & 3;
        const uint32_t dA = base + row * ROWB + seg * 16;
        const __nv_bfloat16* sA = g_X + (size_t)(m0 + row) * HIDDEN + kb * BK + seg * 8;
        CP_ASYNC16(dA, sA);
        const uint32_t dB = base + ABYTES + row * ROWB + seg * 16;
        const __nv_bfloat16* sB = g_W + (size_t)(n0 + row) * HIDDEN + kb * BK + seg * 8;
        CP_ASYNC16(dB, sB);
    }
}

// ---------------- bf16 GEMM (ldmatrix + mma.16816) + fused LSE --------------
// Grid (32 m-tiles [fast], 250 n-tiles). 128 threads, 4 warps (2x2).
// CTA tile 128x128, warp tile 64x64, BK=32, 4-stage cp.async pipeline.
__global__ __launch_bounds__(128, 2)
void gemm_lse_kernel(const float* __restrict__ bias) {
    extern __shared__ char smem[];
    const uint32_t sb = smem_u32(smem);

    const int tid  = threadIdx.x;
    const int lane = tid & 31;
    const int warp = tid >> 5;
    const int g    = lane >> 2;     // 0..7
    const int tig  = lane & 3;      // 0..3
    const int wm   = warp >> 1;     // 0..1 : rows wm*64..+63
    const int wn   = warp & 1;      // 0..1 : cols wn*64..+63
    const int m0   = blockIdx.x * 128;
    const int n0   = blockIdx.y * 128;

    float acc[4][8][4];
#pragma unroll
    for (int i = 0; i < 4; i++)
#pragma unroll
        for (int j = 0; j < 8; j++)
#pragma unroll
            for (int k = 0; k < 4; k++) acc[i][j][k] = 0.f;

    // prologue: 3 stages in flight
    load_stage(sb, 0, 0, m0, n0, tid); CP_COMMIT();
    load_stage(sb, 1, 1, m0, n0, tid); CP_COMMIT();
    load_stage(sb, 2, 2, m0, n0, tid); CP_COMMIT();

    // ldmatrix lane addressing (constant across stages)
    const int a_row  = lane & 15;
    const int a_col8 = (lane >> 4) & 1;            // +8 bf16 col
    const int b_n    = ((lane >> 4) & 1) * 8 + (lane & 7);
    const int b_k8   = (lane >> 3) & 1;            // +8 bf16 col

    for (int kb = 0; kb < NKB; kb++) {
        const int rem = NKB - 1 - kb;
        if (rem >= 2)      CP_WAIT(2);
        else if (rem == 1) CP_WAIT(1);
        else               CP_WAIT(0);
        __syncthreads();

        if (kb + 3 < NKB) {
            load_stage(sb, (kb + 3) & 3, kb + 3, m0, n0, tid);
            CP_COMMIT();
        }

        const uint32_t abase = sb + (kb & 3) * STAGEB;
        const uint32_t bbase = abase + ABYTES;
#pragma unroll
        for (int kh = 0; kh < 2; kh++) {
            uint32_t a[4][4], b[8][2];
            const int acol = kh * 16 + a_col8 * 8;
#pragma unroll
            for (int mt = 0; mt < 4; mt++) {
                const int r = wm * 64 + mt * 16 + a_row;
                LDMATRIX_X4(a[mt][0], a[mt][1], a[mt][2], a[mt][3],
                            abase + r * ROWB + acol * 2);
            }
            const int bcol = kh * 16 + b_k8 * 8;
#pragma unroll
            for (int np = 0; np < 4; np++) {
                const int n = wn * 64 + np * 16 + b_n;
                uint32_t r0, r1, r2, r3;
                LDMATRIX_X4(r0, r1, r2, r3, bbase + n * ROWB + bcol * 2);
                b[np * 2][0] = r0; b[np * 2][1] = r1;
                b[np * 2 + 1][0] = r2; b[np * 2 + 1][1] = r3;
            }
#pragma unroll
            for (int mt = 0; mt < 4; mt++)
#pragma unroll
                for (int nt = 0; nt < 8; nt++)
                    mma16816(acc[mt][nt], a[mt][0], a[mt][1], a[mt][2], a[mt][3],
                             b[nt][0], b[nt][1]);
        }
    }
    __syncthreads();   // SMEM now reusable for reduction

    // --------- fused epilogue: bias + row (max, sumexp) partials ------------
    float2 (*red)[2] = (float2(*)[2])(smem + OFF_RED);
#pragma unroll
    for (int mt = 0; mt < 4; mt++) {
#pragma unroll
        for (int half = 0; half < 2; half++) {
            const int rloc = wm * 64 + mt * 16 + g + half * 8;
            float v[16];
            float vmax = -1e30f;
#pragma unroll
            for (int nt = 0; nt < 8; nt++) {
                const int c0g = n0 + wn * 64 + nt * 8 + tig * 2;
                float v0 = acc[mt][nt][half * 2 + 0] + bias[c0g];
                float v1 = acc[mt][nt][half * 2 + 1] + bias[c0g + 1];
                v[nt * 2]     = v0;
                v[nt * 2 + 1] = v1;
                vmax = fmaxf(vmax, fmaxf(v0, v1));
            }
            float vsum = 0.f;
#pragma unroll
            for (int j = 0; j < 16; j++) vsum += __expf(v[j] - vmax);
#pragma unroll
            for (int off = 1; off < 4; off <<= 1) {
                float om = __shfl_xor_sync(0xffffffffu, vmax, off);
                float os = __shfl_xor_sync(0xffffffffu, vsum, off);
                float nm = fmaxf(vmax, om);
                vsum = vsum * __expf(vmax - nm) + os * __expf(om - nm);
                vmax = nm;
            }
            if (tig == 0) red[rloc][wn] = make_float2(vmax, vsum);
        }
    }
    __syncthreads();
    if (tid < 128) {
        float m = -1e30f, s = 0.f;
#pragma unroll
        for (int w = 0; w < 2; w++) {
            float2 p = red[tid][w];
            float nm = fmaxf(m, p.x);
            s = s * __expf(m - nm) + p.y * __expf(p.x - nm);
            m = nm;
        }
        const size_t idx = (size_t)(m0 + tid) * NP + blockIdx.y;
        g_pmax[idx] = m;
        g_psum[idx] = s;
    }
}

// ---------------- combine partials -> per-token logp ------------------------
__global__ void lse_kernel(const int* __restrict__ target) {
    const int row  = blockIdx.x * 8 + (threadIdx.x >> 5);
    const int lane = threadIdx.x & 31;
    const float* pm = g_pmax + (size_t)row * NP;
    const float* ps = g_psum + (size_t)row * NP;
    float m = -1e30f, s = 0.f;
    for (int j = lane; j < NP; j += 32) {
        float om = pm[j], os = ps[j];
        float nm = fmaxf(m, om);
        s = s * __expf(m - nm) + os * __expf(om - nm);
        m = nm;
    }
#pragma unroll
    for (int off = 16; off; off >>= 1) {
        float om = __shfl_xor_sync(0xffffffffu, m, off);
        float os = __shfl_xor_sync(0xffffffffu, s, off);
        float nm = fmaxf(m, om);
        s = s * __expf(m - nm) + os * __expf(om - nm);
        m = nm;
    }
    if (lane == 0) {
        const float lse = m + logf(s);
        const int t = target[row];
        g_ptok[row] = (t != IGNORE_INDEX) ? (g_tgt[row] - lse) : 0.f;
    }
}

// ---------------- final scalar loss -----------------------------------------
__global__ void final_kernel(const int* __restrict__ target,
                             const float* __restrict__ ref_c,
                             const float* __restrict__ ref_r,
                             float* __restrict__ out) {
    __shared__ float ssum[8];
    __shared__ float scnt[8];
    const int warp = threadIdx.x >> 5;
    const int lane = threadIdx.x & 31;
    float s = 0.f, c = 0.f;
    for (int t = lane; t < SEQ; t += 32) {
        const int row = warp * SEQ + t;
        if (target[row] != IGNORE_INDEX) {
            s += g_ptok[row];
            c += 1.f;
        }
    }
#pragma unroll
    for (int off = 16; off; off >>= 1) {
        s += __shfl_xor_sync(0xffffffffu, s, off);
        c += __shfl_xor_sync(0xffffffffu, c, off);
    }
    if (lane == 0) { ssum[warp] = s; scnt[warp] = c; }
    __syncthreads();
    if (threadIdx.x == 0) {
        float nll_num = 0.f, nll_den = 0.f;
        for (int b = 0; b < 4; b++) { nll_num += ssum[b]; nll_den += scnt[b]; }
        const float nll = -nll_num / nll_den;
        float pl = 0.f;
        for (int i = 0; i < 4; i++) {
            const float ca = ssum[i] / scnt[i] - ref_c[i];
            const float ra = ssum[4 + i] / scnt[4 + i] - ref_r[i];
            const float x  = 0.1f * (ca - ra);
            const float ls = fminf(x, 0.f) - log1pf(expf(-fabsf(x)));
            pl -= ls;
        }
        pl *= 0.25f;
        out[0] = pl + nll;
    }
}

// ---------------- launcher ---------------------------------------------------
extern "C" void kernel_launch(void* const* d_in, const int* in_sizes, int n_in,
                              void* d_out, int out_size) {
    const float* lin_w = (const float*)d_in[0];
    const float* x     = (const float*)d_in[1];
    const int*   tgt   = (const int*)d_in[2];
    const float* ref_c = (const float*)d_in[3];
    const float* ref_r = (const float*)d_in[4];
    const float* bias  = (const float*)d_in[5];
    float* out = (float*)d_out;

    cudaFuncSetAttribute(gemm_lse_kernel,
                         cudaFuncAttributeMaxDynamicSharedMemorySize, SMEM_BYTES);

    __nv_bfloat162* dW;
    __nv_bfloat162* dX;
    cudaGetSymbolAddress((void**)&dW, g_W);
    cudaGetSymbolAddress((void**)&dX, g_X);

    conv_kernel<<<2048, 256>>>((const float4*)lin_w, dW, VOCAB * HIDDEN / 4);
    conv_kernel<<<512, 256>>>((const float4*)x, dX, NTOK * HIDDEN / 4);

    tgt_kernel<<<NTOK / 8, 256>>>(x, lin_w, bias, tgt);

    dim3 grid(NTOK / 128, NP);   // m fast-varying -> B panel shared in-wave
    gemm_lse_kernel<<<grid, 128, SMEM_BYTES>>>(bias);

    lse_kernel<<<NTOK / 8, 256>>>(tgt);
    final_kernel<<<1, 256>>>(tgt, ref_c, ref_r, out);
}